// round 4
// baseline (speedup 1.0000x reference)
#include <cuda_runtime.h>
#include <math.h>

#define N_NODES_ 100000
#define N_EDGES_ 500000
#define HID_ 128
#define NIN_ 16
#define SCAN_B 1024
#define NBLK_ ((N_NODES_ + SCAN_B - 1) / SCAN_B)   // 98

// ---- static scratch (no allocations allowed) ----
__device__ float g_h  [N_NODES_ * HID_];
__device__ float g_hn [N_NODES_ * HID_];
__device__ float g_P  [N_NODES_ * 2 * HID_];   // edge-pred node factors; reused as aggr16
__device__ int   g_deg   [N_NODES_];
__device__ int   g_incl  [N_NODES_];
__device__ int   g_rowptr[N_NODES_ + 1];
__device__ int   g_cursor[N_NODES_];
__device__ int   g_bsum  [NBLK_];
__device__ int   g_boff  [NBLK_];
__device__ int   g_csrc  [N_EDGES_];
__device__ float g_cea   [N_EDGES_];

// ---- transposed weights: W^T[col][k], k contiguous -> packed-f32x2 along k ----
#define OFF_W10T 0                               // [128][16]
#define OFF_W20T 2048                            // [128][128]
#define OFF_W1T  (2048 + 16384)                  // 4 x [128][128]
#define OFF_W2T  (OFF_W1T + 4 * 16384)           // 4 x [128][128]
#define OFF_WPT  (OFF_W2T + 4 * 16384)           // [128][256] (A half k<128, B half k>=128)
#define WT_TOTAL (OFF_WPT + 32768)
__device__ float g_WT[WT_TOTAL];

__device__ __forceinline__ float4 ld4(const float* p) { return *reinterpret_cast<const float4*>(p); }
__device__ __forceinline__ void st4(float* p, float4 v) { *reinterpret_cast<float4*>(p) = v; }
__device__ __forceinline__ float eluf(float x) { return x > 0.f ? x : expm1f(x); }
__device__ __forceinline__ float4 elu4(float4 v) {
    v.x = eluf(v.x); v.y = eluf(v.y); v.z = eluf(v.z); v.w = eluf(v.w); return v;
}

// ---- packed fp32 (f32x2): exact fp32 per lane ----
__device__ __forceinline__ void fma2(unsigned long long& d, unsigned long long a, unsigned long long b) {
    asm("fma.rn.f32x2 %0, %1, %2, %3;" : "=l"(d) : "l"(a), "l"(b), "l"(d));
}
__device__ __forceinline__ float2 upk(unsigned long long v) {
    float2 f;
    asm("mov.b64 {%0, %1}, %2;" : "=f"(f.x), "=f"(f.y) : "l"(v));
    return f;
}

// ---------------------------------------------------------------------------
// GEMV core: 8 rows (s[0..8), row stride KIN) x W^T (rows of length WSTRIDE,
// k contiguous). Lane owns cols lane*4..lane*4+3. Accumulate k in packed
// pairs (both FFMA2 operands naturally 16B-vector-loaded; zero dup MOVs).
// ---------------------------------------------------------------------------
template <int KIN, int WSTRIDE, bool HASB>
__device__ __forceinline__ void gemvT8(const float* s,               // smem [8][KIN]
                                       const float* __restrict__ WT, // W^T base
                                       const float* __restrict__ b,
                                       int lane, float4 out[8])
{
    unsigned long long acc[8][4];
    #pragma unroll
    for (int r = 0; r < 8; r++)
        #pragma unroll
        for (int c = 0; c < 4; c++) acc[r][c] = 0ull;

    const float* w0 = &WT[(lane * 4 + 0) * WSTRIDE];
    const float* w1 = &WT[(lane * 4 + 1) * WSTRIDE];
    const float* w2 = &WT[(lane * 4 + 2) * WSTRIDE];
    const float* w3 = &WT[(lane * 4 + 3) * WSTRIDE];

    #pragma unroll 2
    for (int kg = 0; kg < KIN / 4; kg++) {
        ulonglong2 wv0 = *reinterpret_cast<const ulonglong2*>(&w0[kg * 4]);
        ulonglong2 wv1 = *reinterpret_cast<const ulonglong2*>(&w1[kg * 4]);
        ulonglong2 wv2 = *reinterpret_cast<const ulonglong2*>(&w2[kg * 4]);
        ulonglong2 wv3 = *reinterpret_cast<const ulonglong2*>(&w3[kg * 4]);
        #pragma unroll
        for (int r = 0; r < 8; r++) {
            ulonglong2 a = *reinterpret_cast<const ulonglong2*>(&s[r * KIN + kg * 4]);
            fma2(acc[r][0], a.x, wv0.x); fma2(acc[r][0], a.y, wv0.y);
            fma2(acc[r][1], a.x, wv1.x); fma2(acc[r][1], a.y, wv1.y);
            fma2(acc[r][2], a.x, wv2.x); fma2(acc[r][2], a.y, wv2.y);
            fma2(acc[r][3], a.x, wv3.x); fma2(acc[r][3], a.y, wv3.y);
        }
    }

    float4 bv = make_float4(0.f, 0.f, 0.f, 0.f);
    if (HASB) bv = ld4(&b[lane * 4]);
    #pragma unroll
    for (int r = 0; r < 8; r++) {
        float2 p0 = upk(acc[r][0]), p1 = upk(acc[r][1]);
        float2 p2 = upk(acc[r][2]), p3 = upk(acc[r][3]);
        out[r] = make_float4(p0.x + p0.y + bv.x, p1.x + p1.y + bv.y,
                             p2.x + p2.y + bv.z, p3.x + p3.y + bv.w);
    }
}

// ---------------------------------------------------------------------------
// Weight transpose (once per launch): g_WT[c][k] = W[k][c]
// ---------------------------------------------------------------------------
__global__ void k_transpose_all(const float* __restrict__ W10, const float* __restrict__ W20,
                                const float* __restrict__ W1s, const float* __restrict__ W2s,
                                const float* __restrict__ Wp1)
{
    int i = blockIdx.x * 256 + threadIdx.x;
    if (i < 2048) {                     // W10: [16][128]
        int k = i >> 7, c = i & 127;
        g_WT[OFF_W10T + c * 16 + k] = W10[i];
        return;
    }
    i -= 2048;
    if (i < 16384) {                    // W20: [128][128]
        int k = i >> 7, c = i & 127;
        g_WT[OFF_W20T + c * 128 + k] = W20[i];
        return;
    }
    i -= 16384;
    if (i < 4 * 16384) {                // W1_s: 4 x [128][128]
        int l = i >> 14, j = i & 16383;
        int k = j >> 7, c = j & 127;
        g_WT[OFF_W1T + l * 16384 + c * 128 + k] = W1s[i];
        return;
    }
    i -= 4 * 16384;
    if (i < 4 * 16384) {                // W2_s
        int l = i >> 14, j = i & 16383;
        int k = j >> 7, c = j & 127;
        g_WT[OFF_W2T + l * 16384 + c * 128 + k] = W2s[i];
        return;
    }
    i -= 4 * 16384;
    if (i < 32768) {                    // Wp1: [256][128] -> [128][256]
        int k = i >> 7, c = i & 127;
        g_WT[OFF_WPT + c * 256 + k] = Wp1[i];
    }
}
#define T_ALL_ELEMS (2048 + 16384 + 65536 + 65536 + 32768)

// ---------------------------------------------------------------------------
// CSR build
// ---------------------------------------------------------------------------
__global__ void k_hist(const int* __restrict__ ei) {
    int e = blockIdx.x * blockDim.x + threadIdx.x;
    if (e < N_EDGES_) atomicAdd(&g_deg[ei[N_EDGES_ + e]], 1);
}

__global__ void k_scanA() {
    __shared__ int s[SCAN_B];
    int t = threadIdx.x;
    int g = blockIdx.x * SCAN_B + t;
    int v = (g < N_NODES_) ? g_deg[g] : 0;
    s[t] = v; __syncthreads();
    for (int d = 1; d < SCAN_B; d <<= 1) {
        int u = (t >= d) ? s[t - d] : 0;
        __syncthreads(); s[t] += u; __syncthreads();
    }
    if (g < N_NODES_) g_incl[g] = s[t];
    if (t == SCAN_B - 1) g_bsum[blockIdx.x] = s[t];
}

__global__ void k_scanB() {
    __shared__ int s[128];
    int t = threadIdx.x;
    int v = (t < NBLK_) ? g_bsum[t] : 0;
    s[t] = v; __syncthreads();
    for (int d = 1; d < 128; d <<= 1) {
        int u = (t >= d) ? s[t - d] : 0;
        __syncthreads(); s[t] += u; __syncthreads();
    }
    if (t < NBLK_) g_boff[t] = s[t] - v;
}

__global__ void k_scanC() {
    int g = blockIdx.x * SCAN_B + threadIdx.x;
    if (g >= N_NODES_) return;
    int ex = g_incl[g] - g_deg[g] + g_boff[blockIdx.x];
    g_rowptr[g] = ex;
    g_cursor[g] = ex;
    if (g == N_NODES_ - 1) g_rowptr[N_NODES_] = g_incl[g] + g_boff[blockIdx.x];
}

__global__ void k_fill(const int* __restrict__ ei, const float* __restrict__ ea) {
    int e = blockIdx.x * blockDim.x + threadIdx.x;
    if (e >= N_EDGES_) return;
    int dst = ei[N_EDGES_ + e];
    int slot = atomicAdd(&g_cursor[dst], 1);
    g_csrc[slot] = ei[e];
    g_cea[slot]  = ea[e];
}

// ---------------------------------------------------------------------------
// Layer-0 aggregation (16 features) via CSR gather
// ---------------------------------------------------------------------------
__global__ void k_aggr0(const float* __restrict__ x, const float* __restrict__ We,
                        const float* __restrict__ be, float* __restrict__ aggr)
{
    int t = blockIdx.x * blockDim.x + threadIdx.x;
    int node = t >> 4;
    int f = t & 15;
    if (node >= N_NODES_) return;
    int beg = g_rowptr[node], end = g_rowptr[node + 1];
    float w = We[f], b = be[f], acc = 0.f;
    for (int p = beg; p < end; p++) {
        float m = x[g_csrc[p] * NIN_ + f] + g_cea[p] * w + b;
        acc += fmaxf(m, 0.f);
    }
    aggr[node * NIN_ + f] = acc;
}

// ---------------------------------------------------------------------------
// Layer-0 node MLP. Block = 128 thr / 4 warps; warp owns 8 nodes.
// ---------------------------------------------------------------------------
__global__ void __launch_bounds__(128)
node_mlp16(const float* __restrict__ xin, const float* __restrict__ aggr,
           const float* __restrict__ b1, const float* __restrict__ b2,
           float* __restrict__ hout)
{
    __shared__ __align__(16) float s_in[32 * NIN_];
    __shared__ __align__(16) float s_t [32 * HID_];

    int tid = threadIdx.x;
    int nb  = blockIdx.x * 32;

    for (int i = tid; i < 32 * NIN_; i += 128) {
        int node = i >> 4, k = i & 15;
        int gi = (nb + node) * NIN_ + k;
        s_in[i] = xin[gi] + aggr[gi];
    }
    __syncthreads();

    int w = tid >> 5, lane = tid & 31;
    float4 o[8];
    gemvT8<NIN_, NIN_, true>(&s_in[w * 8 * NIN_], &g_WT[OFF_W10T], b1, lane, o);

    #pragma unroll
    for (int r = 0; r < 8; r++)
        st4(&s_t[(w * 8 + r) * HID_ + lane * 4], elu4(o[r]));
    __syncwarp();

    gemvT8<HID_, HID_, true>(&s_t[w * 8 * HID_], &g_WT[OFF_W20T], b2, lane, o);

    #pragma unroll
    for (int r = 0; r < 8; r++)
        st4(&hout[(nb + w * 8 + r) * HID_ + lane * 4], elu4(o[r]));
}

// ---------------------------------------------------------------------------
// Fused GINE layer (HID -> HID): CSR gather + MLP. 4 warps x 8 nodes.
// ---------------------------------------------------------------------------
__global__ void __launch_bounds__(128)
gine_layer(const float* __restrict__ h,
           const float* __restrict__ We, const float* __restrict__ be,
           const float* __restrict__ WT1, const float* __restrict__ b1,
           const float* __restrict__ WT2, const float* __restrict__ b2,
           float* __restrict__ hout)
{
    __shared__ __align__(16) float s_in[32 * HID_];
    __shared__ __align__(16) float s_t [32 * HID_];

    int tid = threadIdx.x;
    int nb  = blockIdx.x * 32;
    int w = tid >> 5, lane = tid & 31;

    // gather prologue (warp-private rows)
    {
        float4 wv = ld4(&We[lane * 4]);
        float4 bg = ld4(&be[lane * 4]);
        #pragma unroll
        for (int n = 0; n < 8; n++) {
            int node = nb + w * 8 + n;
            float4 acc = ld4(&h[node * HID_ + lane * 4]);
            int beg = g_rowptr[node], end = g_rowptr[node + 1];
            for (int p = beg; p < end; p++) {
                int s = g_csrc[p];
                float we = g_cea[p];
                float4 hv = ld4(&h[s * HID_ + lane * 4]);
                acc.x += fmaxf(fmaf(we, wv.x, hv.x) + bg.x, 0.f);
                acc.y += fmaxf(fmaf(we, wv.y, hv.y) + bg.y, 0.f);
                acc.z += fmaxf(fmaf(we, wv.z, hv.z) + bg.z, 0.f);
                acc.w += fmaxf(fmaf(we, wv.w, hv.w) + bg.w, 0.f);
            }
            st4(&s_in[(w * 8 + n) * HID_ + lane * 4], acc);
        }
    }
    __syncwarp();

    float4 o[8];
    gemvT8<HID_, HID_, true>(&s_in[w * 8 * HID_], WT1, b1, lane, o);

    #pragma unroll
    for (int r = 0; r < 8; r++)
        st4(&s_t[(w * 8 + r) * HID_ + lane * 4], elu4(o[r]));
    __syncwarp();

    gemvT8<HID_, HID_, true>(&s_t[w * 8 * HID_], WT2, b2, lane, o);

    #pragma unroll
    for (int r = 0; r < 8; r++)
        st4(&hout[(nb + w * 8 + r) * HID_ + lane * 4], elu4(o[r]));
}

// ---------------------------------------------------------------------------
// Edge-predictor node factors: P[i,0:128]=h[i]@Wp1[0:128], P[i,128:256]=h[i]@Wp1[128:256]
// Two gemvT8 passes over the same staged input (A half then B half).
// ---------------------------------------------------------------------------
__global__ void __launch_bounds__(128)
k_prednode(const float* __restrict__ h, float* __restrict__ P)
{
    __shared__ __align__(16) float s_in[32 * HID_];

    int tid = threadIdx.x;
    int nb  = blockIdx.x * 32;

    for (int i = tid; i < 32 * HID_ / 4; i += 128)
        st4(&s_in[i * 4], ld4(&h[nb * HID_ + i * 4]));
    __syncthreads();

    int w = tid >> 5, lane = tid & 31;
    float4 o[8];

    gemvT8<HID_, 256, false>(&s_in[w * 8 * HID_], &g_WT[OFF_WPT], nullptr, lane, o);
    #pragma unroll
    for (int r = 0; r < 8; r++)
        st4(&P[(nb + w * 8 + r) * 256 + lane * 4], o[r]);

    gemvT8<HID_, 256, false>(&s_in[w * 8 * HID_], &g_WT[OFF_WPT] + 128, nullptr, lane, o);
    #pragma unroll
    for (int r = 0; r < 8; r++)
        st4(&P[(nb + w * 8 + r) * 256 + 128 + lane * 4], o[r]);
}

// ---------------------------------------------------------------------------
// Per-edge predictor epilogue: out[e] = elu(A[src]+B[dst]+bp1) . Wp2 + bp2
// ---------------------------------------------------------------------------
__global__ void k_prededge(const float* __restrict__ P, const int* __restrict__ ei,
                           const float* __restrict__ bp1, const float* __restrict__ Wp2,
                           const float* __restrict__ bp2, float* __restrict__ out)
{
    int warp = (blockIdx.x * blockDim.x + threadIdx.x) >> 5;
    int lane = threadIdx.x & 31;
    int e0 = warp * 4;
    if (e0 >= N_EDGES_) return;

    float4 bv = ld4(&bp1[lane * 4]);
    float4 w2 = ld4(&Wp2[lane * 4]);
    float c = bp2[0];

    #pragma unroll
    for (int n = 0; n < 4; n++) {
        int e = e0 + n;
        int src = ei[e];
        int dst = ei[N_EDGES_ + e];
        float4 a = ld4(&P[src * 256 + lane * 4]);
        float4 b = ld4(&P[dst * 256 + 128 + lane * 4]);
        float4 t;
        t.x = eluf(a.x + b.x + bv.x);
        t.y = eluf(a.y + b.y + bv.y);
        t.z = eluf(a.z + b.z + bv.z);
        t.w = eluf(a.w + b.w + bv.w);
        float p = t.x * w2.x + t.y * w2.y + t.z * w2.z + t.w * w2.w;
        #pragma unroll
        for (int off = 16; off; off >>= 1)
            p += __shfl_xor_sync(0xffffffffu, p, off);
        if (lane == 0) out[e] = p + c;
    }
}

// ---------------------------------------------------------------------------
extern "C" void kernel_launch(void* const* d_in, const int* in_sizes, int n_in,
                              void* d_out, int out_size)
{
    const float* x    = (const float*)d_in[0];
    const int*   ei   = (const int*)  d_in[1];
    const float* ea   = (const float*)d_in[2];
    const float* We0  = (const float*)d_in[3];
    const float* be0  = (const float*)d_in[4];
    const float* W10  = (const float*)d_in[5];
    const float* b10  = (const float*)d_in[6];
    const float* W20  = (const float*)d_in[7];
    const float* b20  = (const float*)d_in[8];
    const float* We_s = (const float*)d_in[9];
    const float* be_s = (const float*)d_in[10];
    const float* W1_s = (const float*)d_in[11];
    const float* b1_s = (const float*)d_in[12];
    const float* W2_s = (const float*)d_in[13];
    const float* b2_s = (const float*)d_in[14];
    const float* Wp1  = (const float*)d_in[15];
    const float* bp1  = (const float*)d_in[16];
    const float* Wp2  = (const float*)d_in[17];
    const float* bp2  = (const float*)d_in[18];
    float* out = (float*)d_out;

    float *hA, *hB, *P, *WT;
    int *deg;
    cudaGetSymbolAddress((void**)&hA, g_h);
    cudaGetSymbolAddress((void**)&hB, g_hn);
    cudaGetSymbolAddress((void**)&P,  g_P);
    cudaGetSymbolAddress((void**)&WT, g_WT);
    cudaGetSymbolAddress((void**)&deg, g_deg);

    // ---- weight transpose + CSR build ----
    k_transpose_all<<<(T_ALL_ELEMS + 255) / 256, 256>>>(W10, W20, W1_s, W2_s, Wp1);
    cudaMemsetAsync(deg, 0, N_NODES_ * sizeof(int));
    k_hist <<<(N_EDGES_ + 255) / 256, 256>>>(ei);
    k_scanA<<<NBLK_, SCAN_B>>>();
    k_scanB<<<1, 128>>>();
    k_scanC<<<NBLK_, SCAN_B>>>();
    k_fill <<<(N_EDGES_ + 255) / 256, 256>>>(ei, ea);

    // ---- Layer 0 (16 -> 128) ----
    k_aggr0<<<(N_NODES_ * 16 + 255) / 256, 256>>>(x, We0, be0, P);   // reuse P as aggr16
    node_mlp16<<<N_NODES_ / 32, 128>>>(x, P, b10, b20, hA);

    // ---- Layers 1..4 ----
    for (int l = 0; l < 4; l++) {
        gine_layer<<<N_NODES_ / 32, 128>>>(hA,
                                           We_s + l * HID_, be_s + l * HID_,
                                           WT + OFF_W1T + l * 16384, b1_s + l * HID_,
                                           WT + OFF_W2T + l * 16384, b2_s + l * HID_, hB);
        float* t = hA; hA = hB; hB = t;
    }

    // ---- Edge predictor ----
    k_prednode<<<N_NODES_ / 32, 128>>>(hA, P);
    k_prededge<<<(N_EDGES_ / 4 * 32 + 255) / 256, 256>>>(P, ei, bp1, Wp2, bp2, out);
}

// round 5
// speedup vs baseline: 1.6426x; 1.6426x over previous
#include <cuda_runtime.h>
#include <math.h>

#define N_NODES_ 100000
#define N_EDGES_ 500000
#define HID_ 128
#define NIN_ 16
#define SCAN_B 1024
#define NBLK_ ((N_NODES_ + SCAN_B - 1) / SCAN_B)   // 98

typedef unsigned long long u64;

// ---- static scratch (no allocations allowed) ----
__device__ float g_h  [N_NODES_ * HID_];
__device__ float g_hn [N_NODES_ * HID_];
__device__ float g_P  [N_NODES_ * 2 * HID_];   // edge-pred node factors; reused as aggr16
__device__ int   g_deg   [N_NODES_];
__device__ int   g_incl  [N_NODES_];
__device__ int   g_rowptr[N_NODES_ + 1];
__device__ int   g_cursor[N_NODES_];
__device__ int   g_bsum  [NBLK_];
__device__ int   g_boff  [NBLK_];
__device__ int   g_csrc  [N_EDGES_];
__device__ float g_cea   [N_EDGES_];

// ---- duplicated weights: W_dup[k][c] = (w, w) packed u64; k-major, c contiguous
//      (warp-coalesced weight loads, dup-free FFMA2 inner loop) ----
#define OFF_W10D 0                         // [16][128]
#define OFF_W20D 2048                      // [128][128]
#define OFF_W1D  18432                     // 4 x [128][128]
#define OFF_W2D  83968                     // 4 x [128][128]
#define OFF_WPD  149504                    // [256][128]  (A half k<128, B half k>=128)
#define WD_TOTAL 182272
__device__ u64 g_WD[WD_TOTAL];

__device__ __forceinline__ float4 ld4(const float* p) { return *reinterpret_cast<const float4*>(p); }
__device__ __forceinline__ void st4(float* p, float4 v) { *reinterpret_cast<float4*>(p) = v; }
__device__ __forceinline__ float eluf(float x) { return x > 0.f ? x : expm1f(x); }
__device__ __forceinline__ float4 elu4(float4 v) {
    v.x = eluf(v.x); v.y = eluf(v.y); v.z = eluf(v.z); v.w = eluf(v.w); return v;
}

// ---- packed fp32 (f32x2): exact fp32 per lane ----
__device__ __forceinline__ u64 pkdup(float a) {
    u64 r; asm("mov.b64 %0, {%1, %1};" : "=l"(r) : "f"(a)); return r;
}
__device__ __forceinline__ u64 pk2(float lo, float hi) {
    u64 r; asm("mov.b64 %0, {%1, %2};" : "=l"(r) : "f"(lo), "f"(hi)); return r;
}
__device__ __forceinline__ void fma2(u64& d, u64 a, u64 b) {
    asm("fma.rn.f32x2 %0, %1, %2, %3;" : "=l"(d) : "l"(a), "l"(b), "l"(d));
}
__device__ __forceinline__ float2 upk(u64 v) {
    float2 f; asm("mov.b64 {%0, %1}, %2;" : "=f"(f.x), "=f"(f.y) : "l"(v)); return f;
}

// Pack-store one row-pair (a = even row, b = odd row), 4 cols at dst[0..3] (k = lane*4..+3).
__device__ __forceinline__ void st_pair(u64* dst, float4 a, float4 b) {
    ulonglong2 q0, q1;
    q0.x = pk2(a.x, b.x); q0.y = pk2(a.y, b.y);
    q1.x = pk2(a.z, b.z); q1.y = pk2(a.w, b.w);
    *reinterpret_cast<ulonglong2*>(dst)     = q0;
    *reinterpret_cast<ulonglong2*>(dst + 2) = q1;
}

// ---------------------------------------------------------------------------
// GEMV core: 8 rows as 4 packed pairs. sp = smem [4 pairs][KIN] u64
// (sp[p][k] = pack(row2p[k], row2p+1[k])). WD = dup weights [KIN][128] u64.
// Lane owns cols lane*4..+3. Inner loop: coalesced LDG.128 weights,
// broadcast LDS.128 inputs, zero MOVs.
// ---------------------------------------------------------------------------
template <int KIN, bool HASB>
__device__ __forceinline__ void gemvP8(const u64* sp, const u64* __restrict__ WD,
                                       const float* __restrict__ b,
                                       int lane, float4 out[8])
{
    u64 acc[4][4];
    if (HASB) {
        float4 bv = ld4(&b[lane * 4]);
        u64 b0 = pkdup(bv.x), b1 = pkdup(bv.y), b2 = pkdup(bv.z), b3 = pkdup(bv.w);
        #pragma unroll
        for (int p = 0; p < 4; p++) { acc[p][0] = b0; acc[p][1] = b1; acc[p][2] = b2; acc[p][3] = b3; }
    } else {
        #pragma unroll
        for (int p = 0; p < 4; p++)
            #pragma unroll
            for (int c = 0; c < 4; c++) acc[p][c] = 0ull;
    }

    #pragma unroll 2
    for (int kg = 0; kg < KIN / 4; kg++) {
        ulonglong2 a01[4], a23[4];
        #pragma unroll
        for (int p = 0; p < 4; p++) {
            a01[p] = *reinterpret_cast<const ulonglong2*>(&sp[p * KIN + kg * 4]);
            a23[p] = *reinterpret_cast<const ulonglong2*>(&sp[p * KIN + kg * 4 + 2]);
        }
        #pragma unroll
        for (int kk = 0; kk < 4; kk++) {
            const u64* wrow = &WD[(kg * 4 + kk) * HID_ + lane * 4];
            ulonglong2 w01 = *reinterpret_cast<const ulonglong2*>(wrow);
            ulonglong2 w23 = *reinterpret_cast<const ulonglong2*>(wrow + 2);
            #pragma unroll
            for (int p = 0; p < 4; p++) {
                u64 av = (kk == 0) ? a01[p].x : (kk == 1) ? a01[p].y
                       : (kk == 2) ? a23[p].x : a23[p].y;
                fma2(acc[p][0], av, w01.x);
                fma2(acc[p][1], av, w01.y);
                fma2(acc[p][2], av, w23.x);
                fma2(acc[p][3], av, w23.y);
            }
        }
    }

    #pragma unroll
    for (int p = 0; p < 4; p++) {
        float2 c0 = upk(acc[p][0]), c1 = upk(acc[p][1]);
        float2 c2 = upk(acc[p][2]), c3 = upk(acc[p][3]);
        out[2 * p]     = make_float4(c0.x, c1.x, c2.x, c3.x);
        out[2 * p + 1] = make_float4(c0.y, c1.y, c2.y, c3.y);
    }
}

// ---------------------------------------------------------------------------
// Weight duplication (once per launch): g_WD[off + i] = dup(W[i]) — same
// linear layout as source (k-major), so loads/stores are fully coalesced.
// ---------------------------------------------------------------------------
__global__ void k_dup_all(const float* __restrict__ W10, const float* __restrict__ W20,
                          const float* __restrict__ W1s, const float* __restrict__ W2s,
                          const float* __restrict__ Wp1)
{
    int i = blockIdx.x * 256 + threadIdx.x;
    if (i < 2048)          { g_WD[OFF_W10D + i] = pkdup(W10[i]); return; }
    i -= 2048;
    if (i < 16384)         { g_WD[OFF_W20D + i] = pkdup(W20[i]); return; }
    i -= 16384;
    if (i < 65536)         { g_WD[OFF_W1D + i]  = pkdup(W1s[i]); return; }
    i -= 65536;
    if (i < 65536)         { g_WD[OFF_W2D + i]  = pkdup(W2s[i]); return; }
    i -= 65536;
    if (i < 32768)         { g_WD[OFF_WPD + i]  = pkdup(Wp1[i]); }
}

// ---------------------------------------------------------------------------
// CSR build
// ---------------------------------------------------------------------------
__global__ void k_hist(const int* __restrict__ ei) {
    int e = blockIdx.x * blockDim.x + threadIdx.x;
    if (e < N_EDGES_) atomicAdd(&g_deg[ei[N_EDGES_ + e]], 1);
}

__global__ void k_scanA() {
    __shared__ int s[SCAN_B];
    int t = threadIdx.x;
    int g = blockIdx.x * SCAN_B + t;
    int v = (g < N_NODES_) ? g_deg[g] : 0;
    s[t] = v; __syncthreads();
    for (int d = 1; d < SCAN_B; d <<= 1) {
        int u = (t >= d) ? s[t - d] : 0;
        __syncthreads(); s[t] += u; __syncthreads();
    }
    if (g < N_NODES_) g_incl[g] = s[t];
    if (t == SCAN_B - 1) g_bsum[blockIdx.x] = s[t];
}

__global__ void k_scanB() {
    __shared__ int s[128];
    int t = threadIdx.x;
    int v = (t < NBLK_) ? g_bsum[t] : 0;
    s[t] = v; __syncthreads();
    for (int d = 1; d < 128; d <<= 1) {
        int u = (t >= d) ? s[t - d] : 0;
        __syncthreads(); s[t] += u; __syncthreads();
    }
    if (t < NBLK_) g_boff[t] = s[t] - v;
}

__global__ void k_scanC() {
    int g = blockIdx.x * SCAN_B + threadIdx.x;
    if (g >= N_NODES_) return;
    int ex = g_incl[g] - g_deg[g] + g_boff[blockIdx.x];
    g_rowptr[g] = ex;
    g_cursor[g] = ex;
    if (g == N_NODES_ - 1) g_rowptr[N_NODES_] = g_incl[g] + g_boff[blockIdx.x];
}

__global__ void k_fill(const int* __restrict__ ei, const float* __restrict__ ea) {
    int e = blockIdx.x * blockDim.x + threadIdx.x;
    if (e >= N_EDGES_) return;
    int dst = ei[N_EDGES_ + e];
    int slot = atomicAdd(&g_cursor[dst], 1);
    g_csrc[slot] = ei[e];
    g_cea[slot]  = ea[e];
}

// ---------------------------------------------------------------------------
// Layer-0 aggregation (16 features) via CSR gather
// ---------------------------------------------------------------------------
__global__ void k_aggr0(const float* __restrict__ x, const float* __restrict__ We,
                        const float* __restrict__ be, float* __restrict__ aggr)
{
    int t = blockIdx.x * blockDim.x + threadIdx.x;
    int node = t >> 4;
    int f = t & 15;
    if (node >= N_NODES_) return;
    int beg = g_rowptr[node], end = g_rowptr[node + 1];
    float w = We[f], b = be[f], acc = 0.f;
    for (int p = beg; p < end; p++) {
        float m = x[g_csrc[p] * NIN_ + f] + g_cea[p] * w + b;
        acc += fmaxf(m, 0.f);
    }
    aggr[node * NIN_ + f] = acc;
}

// ---------------------------------------------------------------------------
// Layer-0 node MLP. Block = 128 thr / 4 warps; warp owns 8 nodes (4 pairs).
// ---------------------------------------------------------------------------
__global__ void __launch_bounds__(128)
node_mlp16(const float* __restrict__ xin, const float* __restrict__ aggr,
           const float* __restrict__ b1, const float* __restrict__ b2,
           float* __restrict__ hout)
{
    __shared__ __align__(16) u64 s_in[16 * NIN_];   // 16 pairs x 16 k
    __shared__ __align__(16) u64 s_t [16 * HID_];   // 16 pairs x 128 k

    int tid = threadIdx.x;
    int nb  = blockIdx.x * 32;

    for (int i = tid; i < 16 * NIN_; i += 128) {
        int p = i >> 4, k = i & 15;
        int n0 = nb + 2 * p;
        float v0 = xin[n0 * NIN_ + k]       + aggr[n0 * NIN_ + k];
        float v1 = xin[(n0 + 1) * NIN_ + k] + aggr[(n0 + 1) * NIN_ + k];
        s_in[i] = pk2(v0, v1);
    }
    __syncthreads();

    int w = tid >> 5, lane = tid & 31;
    float4 o[8];
    gemvP8<NIN_, true>(&s_in[w * 4 * NIN_], &g_WD[OFF_W10D], b1, lane, o);

    #pragma unroll
    for (int p = 0; p < 4; p++)
        st_pair(&s_t[(w * 4 + p) * HID_ + lane * 4], elu4(o[2 * p]), elu4(o[2 * p + 1]));
    __syncwarp();

    gemvP8<HID_, true>(&s_t[w * 4 * HID_], &g_WD[OFF_W20D], b2, lane, o);

    #pragma unroll
    for (int r = 0; r < 8; r++)
        st4(&hout[(nb + w * 8 + r) * HID_ + lane * 4], elu4(o[r]));
}

// ---------------------------------------------------------------------------
// Fused GINE layer (HID -> HID): CSR gather + MLP. 4 warps x 8 nodes.
// ---------------------------------------------------------------------------
__global__ void __launch_bounds__(128)
gine_layer(const float* __restrict__ h,
           const float* __restrict__ We, const float* __restrict__ be,
           const u64* __restrict__ WD1, const float* __restrict__ b1,
           const u64* __restrict__ WD2, const float* __restrict__ b2,
           float* __restrict__ hout)
{
    __shared__ __align__(16) u64 s_a[16 * HID_];
    __shared__ __align__(16) u64 s_b[16 * HID_];

    int tid = threadIdx.x;
    int nb  = blockIdx.x * 32;
    int w = tid >> 5, lane = tid & 31;

    // gather prologue (warp-private rows); pack node pairs into s_a
    {
        float4 wv = ld4(&We[lane * 4]);
        float4 bg = ld4(&be[lane * 4]);
        float4 prev;
        #pragma unroll
        for (int n = 0; n < 8; n++) {
            int node = nb + w * 8 + n;
            float4 acc = ld4(&h[node * HID_ + lane * 4]);
            int beg = g_rowptr[node], end = g_rowptr[node + 1];
            for (int p = beg; p < end; p++) {
                int s = g_csrc[p];
                float we = g_cea[p];
                float4 hv = ld4(&h[s * HID_ + lane * 4]);
                acc.x += fmaxf(fmaf(we, wv.x, hv.x) + bg.x, 0.f);
                acc.y += fmaxf(fmaf(we, wv.y, hv.y) + bg.y, 0.f);
                acc.z += fmaxf(fmaf(we, wv.z, hv.z) + bg.z, 0.f);
                acc.w += fmaxf(fmaf(we, wv.w, hv.w) + bg.w, 0.f);
            }
            if (n & 1)
                st_pair(&s_a[(w * 4 + (n >> 1)) * HID_ + lane * 4], prev, acc);
            else
                prev = acc;
        }
    }
    __syncwarp();

    float4 o[8];
    gemvP8<HID_, true>(&s_a[w * 4 * HID_], WD1, b1, lane, o);

    #pragma unroll
    for (int p = 0; p < 4; p++)
        st_pair(&s_b[(w * 4 + p) * HID_ + lane * 4], elu4(o[2 * p]), elu4(o[2 * p + 1]));
    __syncwarp();

    gemvP8<HID_, true>(&s_b[w * 4 * HID_], WD2, b2, lane, o);

    #pragma unroll
    for (int r = 0; r < 8; r++)
        st4(&hout[(nb + w * 8 + r) * HID_ + lane * 4], elu4(o[r]));
}

// ---------------------------------------------------------------------------
// Edge-predictor node factors: P[i,0:128]=h[i]@Wp1[0:128], P[i,128:256]=h[i]@Wp1[128:256]
// ---------------------------------------------------------------------------
__global__ void __launch_bounds__(128)
k_prednode(const float* __restrict__ h, float* __restrict__ P)
{
    __shared__ __align__(16) u64 s_in[16 * HID_];

    int tid = threadIdx.x;
    int nb  = blockIdx.x * 32;

    for (int i = tid; i < 16 * HID_; i += 128) {
        int p = i >> 7, k = i & 127;
        int n0 = nb + 2 * p;
        s_in[i] = pk2(h[n0 * HID_ + k], h[(n0 + 1) * HID_ + k]);
    }
    __syncthreads();

    int w = tid >> 5, lane = tid & 31;
    float4 o[8];

    gemvP8<HID_, false>(&s_in[w * 4 * HID_], &g_WD[OFF_WPD], nullptr, lane, o);
    #pragma unroll
    for (int r = 0; r < 8; r++)
        st4(&P[(nb + w * 8 + r) * 256 + lane * 4], o[r]);

    gemvP8<HID_, false>(&s_in[w * 4 * HID_], &g_WD[OFF_WPD] + HID_ * HID_, nullptr, lane, o);
    #pragma unroll
    for (int r = 0; r < 8; r++)
        st4(&P[(nb + w * 8 + r) * 256 + 128 + lane * 4], o[r]);
}

// ---------------------------------------------------------------------------
// Per-edge predictor epilogue: out[e] = elu(A[src]+B[dst]+bp1) . Wp2 + bp2
// ---------------------------------------------------------------------------
__global__ void k_prededge(const float* __restrict__ P, const int* __restrict__ ei,
                           const float* __restrict__ bp1, const float* __restrict__ Wp2,
                           const float* __restrict__ bp2, float* __restrict__ out)
{
    int warp = (blockIdx.x * blockDim.x + threadIdx.x) >> 5;
    int lane = threadIdx.x & 31;
    int e0 = warp * 4;
    if (e0 >= N_EDGES_) return;

    float4 bv = ld4(&bp1[lane * 4]);
    float4 w2 = ld4(&Wp2[lane * 4]);
    float c = bp2[0];

    #pragma unroll
    for (int n = 0; n < 4; n++) {
        int e = e0 + n;
        int src = ei[e];
        int dst = ei[N_EDGES_ + e];
        float4 a = ld4(&P[src * 256 + lane * 4]);
        float4 b = ld4(&P[dst * 256 + 128 + lane * 4]);
        float4 t;
        t.x = eluf(a.x + b.x + bv.x);
        t.y = eluf(a.y + b.y + bv.y);
        t.z = eluf(a.z + b.z + bv.z);
        t.w = eluf(a.w + b.w + bv.w);
        float p = t.x * w2.x + t.y * w2.y + t.z * w2.z + t.w * w2.w;
        #pragma unroll
        for (int off = 16; off; off >>= 1)
            p += __shfl_xor_sync(0xffffffffu, p, off);
        if (lane == 0) out[e] = p + c;
    }
}

// ---------------------------------------------------------------------------
extern "C" void kernel_launch(void* const* d_in, const int* in_sizes, int n_in,
                              void* d_out, int out_size)
{
    const float* x    = (const float*)d_in[0];
    const int*   ei   = (const int*)  d_in[1];
    const float* ea   = (const float*)d_in[2];
    const float* We0  = (const float*)d_in[3];
    const float* be0  = (const float*)d_in[4];
    const float* W10  = (const float*)d_in[5];
    const float* b10  = (const float*)d_in[6];
    const float* W20  = (const float*)d_in[7];
    const float* b20  = (const float*)d_in[8];
    const float* We_s = (const float*)d_in[9];
    const float* be_s = (const float*)d_in[10];
    const float* W1_s = (const float*)d_in[11];
    const float* b1_s = (const float*)d_in[12];
    const float* W2_s = (const float*)d_in[13];
    const float* b2_s = (const float*)d_in[14];
    const float* Wp1  = (const float*)d_in[15];
    const float* bp1  = (const float*)d_in[16];
    const float* Wp2  = (const float*)d_in[17];
    const float* bp2  = (const float*)d_in[18];
    float* out = (float*)d_out;

    float *hA, *hB, *P;
    u64 *WD;
    int *deg;
    cudaGetSymbolAddress((void**)&hA, g_h);
    cudaGetSymbolAddress((void**)&hB, g_hn);
    cudaGetSymbolAddress((void**)&P,  g_P);
    cudaGetSymbolAddress((void**)&WD, g_WD);
    cudaGetSymbolAddress((void**)&deg, g_deg);

    // ---- weight dup + CSR build ----
    k_dup_all<<<(WD_TOTAL + 255) / 256, 256>>>(W10, W20, W1_s, W2_s, Wp1);
    cudaMemsetAsync(deg, 0, N_NODES_ * sizeof(int));
    k_hist <<<(N_EDGES_ + 255) / 256, 256>>>(ei);
    k_scanA<<<NBLK_, SCAN_B>>>();
    k_scanB<<<1, 128>>>();
    k_scanC<<<NBLK_, SCAN_B>>>();
    k_fill <<<(N_EDGES_ + 255) / 256, 256>>>(ei, ea);

    // ---- Layer 0 (16 -> 128) ----
    k_aggr0<<<(N_NODES_ * 16 + 255) / 256, 256>>>(x, We0, be0, P);   // reuse P as aggr16
    node_mlp16<<<N_NODES_ / 32, 128>>>(x, P, b10, b20, hA);

    // ---- Layers 1..4 ----
    for (int l = 0; l < 4; l++) {
        gine_layer<<<N_NODES_ / 32, 128>>>(hA,
                                           We_s + l * HID_, be_s + l * HID_,
                                           WD + OFF_W1D + l * 16384, b1_s + l * HID_,
                                           WD + OFF_W2D + l * 16384, b2_s + l * HID_, hB);
        float* t = hA; hA = hB; hB = t;
    }

    // ---- Edge predictor ----
    k_prednode<<<N_NODES_ / 32, 128>>>(hA, P);
    k_prededge<<<(N_EDGES_ / 4 * 32 + 255) / 256, 256>>>(P, ei, bp1, Wp2, bp2, out);
}

// round 6
// speedup vs baseline: 2.1240x; 1.2931x over previous
#include <cuda_runtime.h>
#include <math.h>

#define N_NODES_ 100000
#define N_EDGES_ 500000
#define HID_ 128
#define NIN_ 16
#define SCAN_B 1024
#define NBLK_ ((N_NODES_ + SCAN_B - 1) / SCAN_B)   // 98
#define NODE_BLKS ((N_NODES_ + 63) / 64)           // 1563
#define SSTR 132                                   // smem row stride (floats), conflict-free

typedef unsigned int uint32;

// ---- static scratch (no allocations allowed) ----
__device__ float g_h  [N_NODES_ * HID_];
__device__ float g_hn [N_NODES_ * HID_];
__device__ float g_P  [N_NODES_ * 2 * HID_];   // edge-pred node factors; reused as aggr16
__device__ int   g_deg   [N_NODES_];
__device__ int   g_incl  [N_NODES_];
__device__ int   g_rowptr[N_NODES_ + 1];
__device__ int   g_cursor[N_NODES_];
__device__ int   g_bsum  [NBLK_];
__device__ int   g_boff  [NBLK_];
__device__ int   g_csrc  [N_EDGES_];
__device__ float g_cea   [N_EDGES_];

// ---- fragment-ordered TF32 hi/lo weights: [kstep][ntile][lane] = {bhi0,bhi1,blo0,blo1}
#define WF_W10 0                 // K=16 : 2*16*32   = 1024
#define WF_W20 1024              // K=128: 16*16*32  = 8192
#define WF_W1  9216              // 4 x 8192
#define WF_W2  41984             // 4 x 8192
#define WF_WPA 74752             // Wp1 rows 0..127
#define WF_WPB 82944             // Wp1 rows 128..255
#define WF_TOTAL 91136
__device__ uint4 g_WF[WF_TOTAL];

__device__ __forceinline__ float4 ld4(const float* p) { return *reinterpret_cast<const float4*>(p); }
__device__ __forceinline__ void st4(float* p, float4 v) { *reinterpret_cast<float4*>(p) = v; }
__device__ __forceinline__ float eluf(float x) { return x > 0.f ? x : expm1f(x); }

// ---- tf32 helpers ----
__device__ __forceinline__ uint32 tf32_hi(float f) {
    uint32 r; asm("cvt.rna.tf32.f32 %0, %1;" : "=r"(r) : "f"(f)); return r;
}
__device__ __forceinline__ uint32 tf32_lo(float f, uint32 hi) {
    return tf32_hi(f - __uint_as_float(hi));
}

// D += A(tf32) * B(tf32), m16n8k8
__device__ __forceinline__ void mma8(float c[4], uint32 a0, uint32 a1, uint32 a2, uint32 a3,
                                     uint32 b0, uint32 b1)
{
    asm volatile(
        "mma.sync.aligned.m16n8k8.row.col.f32.tf32.tf32.f32 "
        "{%0,%1,%2,%3}, {%4,%5,%6,%7}, {%8,%9}, {%0,%1,%2,%3};"
        : "+f"(c[0]), "+f"(c[1]), "+f"(c[2]), "+f"(c[3])
        : "r"(a0), "r"(a1), "r"(a2), "r"(a3), "r"(b0), "r"(b1));
}

// ---------------------------------------------------------------------------
// One MMA phase: warp computes C[16 rows x 128 cols] = Zw @ W (3xTF32 split).
// Zw: warp's 16 rows in smem (stride SSTR). WF: fragment table for this W.
// ---------------------------------------------------------------------------
template <int KSTEPS>
__device__ __forceinline__ void mma_phase(const float* Zw, const uint4* __restrict__ WF,
                                          int lane, float c[16][4])
{
    int g = lane >> 2, t = lane & 3;
    #pragma unroll
    for (int nt = 0; nt < 16; nt++) { c[nt][0] = 0.f; c[nt][1] = 0.f; c[nt][2] = 0.f; c[nt][3] = 0.f; }

    #pragma unroll 1
    for (int ks = 0; ks < KSTEPS; ks++) {
        float z0 = Zw[g * SSTR + ks * 8 + t];
        float z1 = Zw[(g + 8) * SSTR + ks * 8 + t];
        float z2 = Zw[g * SSTR + ks * 8 + t + 4];
        float z3 = Zw[(g + 8) * SSTR + ks * 8 + t + 4];
        uint32 ah0 = tf32_hi(z0), ah1 = tf32_hi(z1), ah2 = tf32_hi(z2), ah3 = tf32_hi(z3);
        uint32 al0 = tf32_lo(z0, ah0), al1 = tf32_lo(z1, ah1);
        uint32 al2 = tf32_lo(z2, ah2), al3 = tf32_lo(z3, ah3);
        const uint4* wrow = &WF[ks * 16 * 32 + lane];
        #pragma unroll
        for (int nt = 0; nt < 16; nt++) {
            uint4 wf = wrow[nt * 32];
            mma8(c[nt], ah0, ah1, ah2, ah3, wf.x, wf.y);   // Ahi*Bhi
            mma8(c[nt], al0, al1, al2, al3, wf.x, wf.y);   // Alo*Bhi
            mma8(c[nt], ah0, ah1, ah2, ah3, wf.z, wf.w);   // Ahi*Blo
        }
    }
}

// ---------------------------------------------------------------------------
// Weight fragment prep (once per launch)
// ---------------------------------------------------------------------------
__global__ void k_wfrag(const float* __restrict__ W10, const float* __restrict__ W20,
                        const float* __restrict__ W1s, const float* __restrict__ W2s,
                        const float* __restrict__ Wp1)
{
    int i = blockIdx.x * 256 + threadIdx.x;
    if (i >= WF_TOTAL) return;
    const float* W; int idx;
    if (i < 1024)        { W = W10; idx = i; }
    else if (i < 9216)   { W = W20; idx = i - 1024; }
    else if (i < 41984)  { int j = i - 9216;  W = W1s + (j >> 13) * 16384; idx = j & 8191; }
    else if (i < 74752)  { int j = i - 41984; W = W2s + (j >> 13) * 16384; idx = j & 8191; }
    else if (i < 82944)  { W = Wp1;           idx = i - 74752; }
    else                 { W = Wp1 + 16384;   idx = i - 82944; }
    int lane = idx & 31, nt = (idx >> 5) & 15, ks = idx >> 9;
    int k0 = ks * 8 + (lane & 3);
    int n  = nt * 8 + (lane >> 2);
    float w0 = W[k0 * 128 + n];
    float w1 = W[(k0 + 4) * 128 + n];
    uint32 h0 = tf32_hi(w0), h1 = tf32_hi(w1);
    g_WF[i] = make_uint4(h0, h1, tf32_lo(w0, h0), tf32_lo(w1, h1));
}

// ---------------------------------------------------------------------------
// CSR build
// ---------------------------------------------------------------------------
__global__ void k_hist(const int* __restrict__ ei) {
    int e = blockIdx.x * blockDim.x + threadIdx.x;
    if (e < N_EDGES_) atomicAdd(&g_deg[ei[N_EDGES_ + e]], 1);
}

__global__ void k_scanA() {
    __shared__ int s[SCAN_B];
    int t = threadIdx.x;
    int g = blockIdx.x * SCAN_B + t;
    int v = (g < N_NODES_) ? g_deg[g] : 0;
    s[t] = v; __syncthreads();
    for (int d = 1; d < SCAN_B; d <<= 1) {
        int u = (t >= d) ? s[t - d] : 0;
        __syncthreads(); s[t] += u; __syncthreads();
    }
    if (g < N_NODES_) g_incl[g] = s[t];
    if (t == SCAN_B - 1) g_bsum[blockIdx.x] = s[t];
}

__global__ void k_scanB() {
    __shared__ int s[128];
    int t = threadIdx.x;
    int v = (t < NBLK_) ? g_bsum[t] : 0;
    s[t] = v; __syncthreads();
    for (int d = 1; d < 128; d <<= 1) {
        int u = (t >= d) ? s[t - d] : 0;
        __syncthreads(); s[t] += u; __syncthreads();
    }
    if (t < NBLK_) g_boff[t] = s[t] - v;
}

__global__ void k_scanC() {
    int g = blockIdx.x * SCAN_B + threadIdx.x;
    if (g >= N_NODES_) return;
    int ex = g_incl[g] - g_deg[g] + g_boff[blockIdx.x];
    g_rowptr[g] = ex;
    g_cursor[g] = ex;
    if (g == N_NODES_ - 1) g_rowptr[N_NODES_] = g_incl[g] + g_boff[blockIdx.x];
}

__global__ void k_fill(const int* __restrict__ ei, const float* __restrict__ ea) {
    int e = blockIdx.x * blockDim.x + threadIdx.x;
    if (e >= N_EDGES_) return;
    int dst = ei[N_EDGES_ + e];
    int slot = atomicAdd(&g_cursor[dst], 1);
    g_csrc[slot] = ei[e];
    g_cea[slot]  = ea[e];
}

// ---------------------------------------------------------------------------
// Layer-0 aggregation (16 features) via CSR gather
// ---------------------------------------------------------------------------
__global__ void k_aggr0(const float* __restrict__ x, const float* __restrict__ We,
                        const float* __restrict__ be, float* __restrict__ aggr)
{
    int t = blockIdx.x * blockDim.x + threadIdx.x;
    int node = t >> 4;
    int f = t & 15;
    if (node >= N_NODES_) return;
    int beg = g_rowptr[node], end = g_rowptr[node + 1];
    float w = We[f], b = be[f], acc = 0.f;
    for (int p = beg; p < end; p++) {
        float m = x[g_csrc[p] * NIN_ + f] + g_cea[p] * w + b;
        acc += fmaxf(m, 0.f);
    }
    aggr[node * NIN_ + f] = acc;
}

// ---------------------------------------------------------------------------
// Layer-0 node MLP (tensor core): 64 nodes/block, 4 warps x 16 rows.
// ---------------------------------------------------------------------------
__global__ void __launch_bounds__(128)
node_mlp16_tc(const float* __restrict__ xin, const float* __restrict__ aggr,
              const float* __restrict__ b1, const float* __restrict__ b2,
              float* __restrict__ hout)
{
    __shared__ __align__(16) float Z[64 * SSTR];

    int tid = threadIdx.x, w = tid >> 5, lane = tid & 31;
    int nb = blockIdx.x * 64;

    // stage x+aggr (16 cols) for 64 rows
    for (int i = tid; i < 64 * 4; i += 128) {
        int row = i >> 2, c4 = i & 3;
        int node = nb + row;
        float4 v = make_float4(0.f, 0.f, 0.f, 0.f);
        if (node < N_NODES_) {
            float4 a = ld4(&xin[node * NIN_ + c4 * 4]);
            float4 g = ld4(&aggr[node * NIN_ + c4 * 4]);
            v = make_float4(a.x + g.x, a.y + g.y, a.z + g.z, a.w + g.w);
        }
        st4(&Z[row * SSTR + c4 * 4], v);
    }
    __syncthreads();

    float c[16][4];
    const float* Zw = &Z[w * 16 * SSTR];
    int g = lane >> 2, t = lane & 3;

    mma_phase<2>(Zw, &g_WF[WF_W10], lane, c);
    __syncwarp();
    #pragma unroll
    for (int nt = 0; nt < 16; nt++) {
        int col = nt * 8 + 2 * t;
        float2 bb = *(const float2*)&b1[col];
        float2 e0 = make_float2(eluf(c[nt][0] + bb.x), eluf(c[nt][1] + bb.y));
        float2 e1 = make_float2(eluf(c[nt][2] + bb.x), eluf(c[nt][3] + bb.y));
        *(float2*)&Z[(w * 16 + g) * SSTR + col]     = e0;
        *(float2*)&Z[(w * 16 + g + 8) * SSTR + col] = e1;
    }
    __syncwarp();

    mma_phase<16>(Zw, &g_WF[WF_W20], lane, c);
    int n0 = nb + w * 16 + g;
    #pragma unroll
    for (int nt = 0; nt < 16; nt++) {
        int col = nt * 8 + 2 * t;
        float2 bb = *(const float2*)&b2[col];
        float2 e0 = make_float2(eluf(c[nt][0] + bb.x), eluf(c[nt][1] + bb.y));
        float2 e1 = make_float2(eluf(c[nt][2] + bb.x), eluf(c[nt][3] + bb.y));
        if (n0 < N_NODES_)     *(float2*)&hout[n0 * HID_ + col]       = e0;
        if (n0 + 8 < N_NODES_) *(float2*)&hout[(n0 + 8) * HID_ + col] = e1;
    }
}

// ---------------------------------------------------------------------------
// Fused GINE layer (tensor core): CSR gather + 2 MMA phases.
// ---------------------------------------------------------------------------
__global__ void __launch_bounds__(128)
gine_tc(const float* __restrict__ h,
        const float* __restrict__ We, const float* __restrict__ be,
        const uint4* __restrict__ WF1, const float* __restrict__ b1,
        const uint4* __restrict__ WF2, const float* __restrict__ b2,
        float* __restrict__ hout)
{
    __shared__ __align__(16) float Z[64 * SSTR];

    int tid = threadIdx.x, w = tid >> 5, lane = tid & 31;
    int nb = blockIdx.x * 64;

    // gather prologue: each warp fills its 16 rows
    {
        float4 wv = ld4(&We[lane * 4]);
        float4 bg = ld4(&be[lane * 4]);
        for (int n = 0; n < 16; n++) {
            int node = nb + w * 16 + n;
            float4 acc = make_float4(0.f, 0.f, 0.f, 0.f);
            if (node < N_NODES_) {
                acc = ld4(&h[node * HID_ + lane * 4]);
                int beg = g_rowptr[node], end = g_rowptr[node + 1];
                for (int p = beg; p < end; p++) {
                    int s = g_csrc[p];
                    float we = g_cea[p];
                    float4 hv = ld4(&h[s * HID_ + lane * 4]);
                    acc.x += fmaxf(fmaf(we, wv.x, hv.x) + bg.x, 0.f);
                    acc.y += fmaxf(fmaf(we, wv.y, hv.y) + bg.y, 0.f);
                    acc.z += fmaxf(fmaf(we, wv.z, hv.z) + bg.z, 0.f);
                    acc.w += fmaxf(fmaf(we, wv.w, hv.w) + bg.w, 0.f);
                }
            }
            st4(&Z[(w * 16 + n) * SSTR + lane * 4], acc);
        }
    }
    __syncwarp();

    float c[16][4];
    const float* Zw = &Z[w * 16 * SSTR];
    int g = lane >> 2, t = lane & 3;

    mma_phase<16>(Zw, WF1, lane, c);
    __syncwarp();
    #pragma unroll
    for (int nt = 0; nt < 16; nt++) {
        int col = nt * 8 + 2 * t;
        float2 bb = *(const float2*)&b1[col];
        float2 e0 = make_float2(eluf(c[nt][0] + bb.x), eluf(c[nt][1] + bb.y));
        float2 e1 = make_float2(eluf(c[nt][2] + bb.x), eluf(c[nt][3] + bb.y));
        *(float2*)&Z[(w * 16 + g) * SSTR + col]     = e0;
        *(float2*)&Z[(w * 16 + g + 8) * SSTR + col] = e1;
    }
    __syncwarp();

    mma_phase<16>(Zw, WF2, lane, c);
    int n0 = nb + w * 16 + g;
    #pragma unroll
    for (int nt = 0; nt < 16; nt++) {
        int col = nt * 8 + 2 * t;
        float2 bb = *(const float2*)&b2[col];
        float2 e0 = make_float2(eluf(c[nt][0] + bb.x), eluf(c[nt][1] + bb.y));
        float2 e1 = make_float2(eluf(c[nt][2] + bb.x), eluf(c[nt][3] + bb.y));
        if (n0 < N_NODES_)     *(float2*)&hout[n0 * HID_ + col]       = e0;
        if (n0 + 8 < N_NODES_) *(float2*)&hout[(n0 + 8) * HID_ + col] = e1;
    }
}

// ---------------------------------------------------------------------------
// Edge-predictor node factors (tensor core): P[i,0:128], P[i,128:256]
// ---------------------------------------------------------------------------
__global__ void __launch_bounds__(128)
k_prednode_tc(const float* __restrict__ h, float* __restrict__ P)
{
    __shared__ __align__(16) float Z[64 * SSTR];

    int tid = threadIdx.x, w = tid >> 5, lane = tid & 31;
    int nb = blockIdx.x * 64;

    for (int i = tid; i < 64 * 32; i += 128) {
        int row = i >> 5, c4 = i & 31;
        int node = nb + row;
        float4 v = make_float4(0.f, 0.f, 0.f, 0.f);
        if (node < N_NODES_) v = ld4(&h[node * HID_ + c4 * 4]);
        st4(&Z[row * SSTR + c4 * 4], v);
    }
    __syncthreads();

    float c[16][4];
    const float* Zw = &Z[w * 16 * SSTR];
    int g = lane >> 2, t = lane & 3;
    int n0 = nb + w * 16 + g;

    mma_phase<16>(Zw, &g_WF[WF_WPA], lane, c);
    #pragma unroll
    for (int nt = 0; nt < 16; nt++) {
        int col = nt * 8 + 2 * t;
        if (n0 < N_NODES_)     *(float2*)&P[n0 * 256 + col]       = make_float2(c[nt][0], c[nt][1]);
        if (n0 + 8 < N_NODES_) *(float2*)&P[(n0 + 8) * 256 + col] = make_float2(c[nt][2], c[nt][3]);
    }

    mma_phase<16>(Zw, &g_WF[WF_WPB], lane, c);
    #pragma unroll
    for (int nt = 0; nt < 16; nt++) {
        int col = nt * 8 + 2 * t;
        if (n0 < N_NODES_)     *(float2*)&P[n0 * 256 + 128 + col]       = make_float2(c[nt][0], c[nt][1]);
        if (n0 + 8 < N_NODES_) *(float2*)&P[(n0 + 8) * 256 + 128 + col] = make_float2(c[nt][2], c[nt][3]);
    }
}

// ---------------------------------------------------------------------------
// Per-edge predictor epilogue: out[e] = elu(A[src]+B[dst]+bp1) . Wp2 + bp2
// ---------------------------------------------------------------------------
__global__ void k_prededge(const float* __restrict__ P, const int* __restrict__ ei,
                           const float* __restrict__ bp1, const float* __restrict__ Wp2,
                           const float* __restrict__ bp2, float* __restrict__ out)
{
    int warp = (blockIdx.x * blockDim.x + threadIdx.x) >> 5;
    int lane = threadIdx.x & 31;
    int e0 = warp * 4;
    if (e0 >= N_EDGES_) return;

    float4 bv = ld4(&bp1[lane * 4]);
    float4 w2 = ld4(&Wp2[lane * 4]);
    float cc = bp2[0];

    #pragma unroll
    for (int n = 0; n < 4; n++) {
        int e = e0 + n;
        int src = ei[e];
        int dst = ei[N_EDGES_ + e];
        float4 a = ld4(&P[src * 256 + lane * 4]);
        float4 b = ld4(&P[dst * 256 + 128 + lane * 4]);
        float4 tt;
        tt.x = eluf(a.x + b.x + bv.x);
        tt.y = eluf(a.y + b.y + bv.y);
        tt.z = eluf(a.z + b.z + bv.z);
        tt.w = eluf(a.w + b.w + bv.w);
        float p = tt.x * w2.x + tt.y * w2.y + tt.z * w2.z + tt.w * w2.w;
        #pragma unroll
        for (int off = 16; off; off >>= 1)
            p += __shfl_xor_sync(0xffffffffu, p, off);
        if (lane == 0) out[e] = p + cc;
    }
}

// ---------------------------------------------------------------------------
extern "C" void kernel_launch(void* const* d_in, const int* in_sizes, int n_in,
                              void* d_out, int out_size)
{
    const float* x    = (const float*)d_in[0];
    const int*   ei   = (const int*)  d_in[1];
    const float* ea   = (const float*)d_in[2];
    const float* We0  = (const float*)d_in[3];
    const float* be0  = (const float*)d_in[4];
    const float* W10  = (const float*)d_in[5];
    const float* b10  = (const float*)d_in[6];
    const float* W20  = (const float*)d_in[7];
    const float* b20  = (const float*)d_in[8];
    const float* We_s = (const float*)d_in[9];
    const float* be_s = (const float*)d_in[10];
    const float* W1_s = (const float*)d_in[11];
    const float* b1_s = (const float*)d_in[12];
    const float* W2_s = (const float*)d_in[13];
    const float* b2_s = (const float*)d_in[14];
    const float* Wp1  = (const float*)d_in[15];
    const float* bp1  = (const float*)d_in[16];
    const float* Wp2  = (const float*)d_in[17];
    const float* bp2  = (const float*)d_in[18];
    float* out = (float*)d_out;

    float *hA, *hB, *P;
    uint4* WF;
    int *deg;
    cudaGetSymbolAddress((void**)&hA, g_h);
    cudaGetSymbolAddress((void**)&hB, g_hn);
    cudaGetSymbolAddress((void**)&P,  g_P);
    cudaGetSymbolAddress((void**)&WF, g_WF);
    cudaGetSymbolAddress((void**)&deg, g_deg);

    // ---- weight fragment prep + CSR build ----
    k_wfrag<<<(WF_TOTAL + 255) / 256, 256>>>(W10, W20, W1_s, W2_s, Wp1);
    cudaMemsetAsync(deg, 0, N_NODES_ * sizeof(int));
    k_hist <<<(N_EDGES_ + 255) / 256, 256>>>(ei);
    k_scanA<<<NBLK_, SCAN_B>>>();
    k_scanB<<<1, 128>>>();
    k_scanC<<<NBLK_, SCAN_B>>>();
    k_fill <<<(N_EDGES_ + 255) / 256, 256>>>(ei, ea);

    // ---- Layer 0 (16 -> 128) ----
    k_aggr0<<<(N_NODES_ * 16 + 255) / 256, 256>>>(x, We0, be0, P);   // reuse P as aggr16
    node_mlp16_tc<<<NODE_BLKS, 128>>>(x, P, b10, b20, hA);

    // ---- Layers 1..4 ----
    for (int l = 0; l < 4; l++) {
        gine_tc<<<NODE_BLKS, 128>>>(hA,
                                    We_s + l * HID_, be_s + l * HID_,
                                    WF + WF_W1 + l * 8192, b1_s + l * HID_,
                                    WF + WF_W2 + l * 8192, b2_s + l * HID_, hB);
        float* t = hA; hA = hB; hB = t;
    }

    // ---- Edge predictor ----
    k_prednode_tc<<<NODE_BLKS, 128>>>(hA, P);
    k_prededge<<<(N_EDGES_ / 4 * 32 + 255) / 256, 256>>>(P, ei, bp1, Wp2, bp2, out);
}